// round 8
// baseline (speedup 1.0000x reference)
#include <cuda_runtime.h>
#include <cuda_bf16.h>

#define NN 100000
#define EE 3200000

// ---------------- static device scratch (no cudaMalloc allowed) ----------------
__device__ float g_deg[NN];
__device__ float g_dis[NN];
__device__ int   g_cnt[NN];
__device__ int   g_rowoff[NN + 1];
__device__ int   g_cursor[NN];
__device__ int   g_bsum[128];
__device__ int   g_is32;                 // 1 if edge_index is int32, 0 if int64
__device__ int2  g_csr[EE];              // packed {src, float_bits(norm_w)}
__device__ float g_H[3 * NN * 128];      // hop buffers h1..h3 (max d=128); also P/T for layer 3
__device__ float g_OutA[NN * 128];
__device__ float g_OutB[NN * 128];

// ---------------- dtype probe: is edge_index int32 or int64? ----------------
__global__ void k_detect(const void* ei) {
    const long long* p = (const long long*)ei;
    long long v = p[threadIdx.x];
    int bad = (v < 0 || v >= NN) ? 1 : 0;
    int any = __syncthreads_or(bad);
    if (threadIdx.x == 0) g_is32 = any;
}

__device__ __forceinline__ void load_edge(const void* ei, int e, int& s, int& d) {
    if (g_is32) {
        const int* p = (const int*)ei;
        s = p[e];
        d = p[EE + e];
    } else {
        const long long* p = (const long long*)ei;
        s = (int)p[e];
        d = (int)p[(size_t)EE + e];
    }
}

// ---------------- preprocessing ----------------
__global__ void k_zero() {
    int i = blockIdx.x * blockDim.x + threadIdx.x;
    if (i < NN) { g_deg[i] = 0.f; g_cnt[i] = 0; }
}

__global__ void k_deg(const void* ei, const float* __restrict__ w) {
    int e = blockIdx.x * blockDim.x + threadIdx.x;
    if (e < EE) {
        int s, d;
        load_edge(ei, e, s, d);
        atomicAdd(&g_deg[d], w[e]);
        atomicAdd(&g_cnt[d], 1);
    }
}

// 3-kernel exclusive scan of g_cnt -> g_rowoff (dis folded into scan3)
__global__ void k_scan1() {
    __shared__ int s[1024];
    int t = threadIdx.x, b = blockIdx.x;
    int i = b * 1024 + t;
    int v = (i < NN) ? g_cnt[i] : 0;
    s[t] = v; __syncthreads();
    #pragma unroll
    for (int off = 1; off < 1024; off <<= 1) {
        int add = (t >= off) ? s[t - off] : 0;
        __syncthreads();
        s[t] += add;
        __syncthreads();
    }
    if (i < NN) g_rowoff[i] = s[t] - v;   // exclusive within block
    if (t == 1023) g_bsum[b] = s[1023];
}

__global__ void k_scan2(int nblk) {
    __shared__ int s[128];
    int t = threadIdx.x;
    int v = (t < nblk) ? g_bsum[t] : 0;
    s[t] = v; __syncthreads();
    #pragma unroll
    for (int off = 1; off < 128; off <<= 1) {
        int add = (t >= off) ? s[t - off] : 0;
        __syncthreads();
        s[t] += add;
        __syncthreads();
    }
    g_bsum[t] = s[t] - v;                  // exclusive
}

__global__ void k_scan3() {
    int i = blockIdx.x * blockDim.x + threadIdx.x;
    if (i < NN) {
        int v = g_rowoff[i] + g_bsum[i >> 10];
        g_rowoff[i] = v;
        g_cursor[i] = v;
        float dg = g_deg[i];
        g_dis[i] = (dg > 0.f) ? rsqrtf(dg) : 0.f;
    }
    if (i == 0) g_rowoff[NN] = EE;
}

__global__ void k_fill(const void* ei, const float* __restrict__ w) {
    int e = blockIdx.x * blockDim.x + threadIdx.x;
    if (e < EE) {
        int s, d;
        load_edge(ei, e, s, d);
        float nr = g_dis[s] * w[e] * g_dis[d];
        int pos = atomicAdd(&g_cursor[d], 1);
        g_csr[pos] = make_int2(s, __float_as_int(nr));
    }
}

// ---------------- SpMM d=128: warp per node, float4 gathers, 8-edge shfl broadcast,
//                  edge-tile prefetch pipeline ----------------
__global__ void __launch_bounds__(256)
k_spmm128(const float* __restrict__ inp, float* __restrict__ outp) {
    int lane = threadIdx.x & 31;
    int n = blockIdx.x * 8 + (threadIdx.x >> 5);     // NN % 8 == 0
    int start = __ldg(&g_rowoff[n]), end = __ldg(&g_rowoff[n + 1]);
    float4 acc = make_float4(0.f, 0.f, 0.f, 0.f);
    const float* col = inp + lane * 4;

    // prefetch first edge tile
    int s = 0; float w = 0.f;
    {
        int i = start + lane;
        if (i < end) {
            int2 e = __ldg(&g_csr[i]);
            s = e.x; w = __int_as_float(e.y);
        }
    }
    for (int base = start; base < end; base += 32) {
        // prefetch next tile while current is consumed below
        int sn = 0; float wn = 0.f;
        int inext = base + 32 + lane;
        if (inext < end) {
            int2 e = __ldg(&g_csr[inext]);
            sn = e.x; wn = __int_as_float(e.y);
        }
        int c = min(32, end - base);
        int j = 0;
        for (; j + 8 <= c; j += 8) {
            int   s0 = __shfl_sync(0xFFFFFFFFu, s, j + 0);
            int   s1 = __shfl_sync(0xFFFFFFFFu, s, j + 1);
            int   s2 = __shfl_sync(0xFFFFFFFFu, s, j + 2);
            int   s3 = __shfl_sync(0xFFFFFFFFu, s, j + 3);
            int   s4 = __shfl_sync(0xFFFFFFFFu, s, j + 4);
            int   s5 = __shfl_sync(0xFFFFFFFFu, s, j + 5);
            int   s6 = __shfl_sync(0xFFFFFFFFu, s, j + 6);
            int   s7 = __shfl_sync(0xFFFFFFFFu, s, j + 7);
            float w0 = __shfl_sync(0xFFFFFFFFu, w, j + 0);
            float w1 = __shfl_sync(0xFFFFFFFFu, w, j + 1);
            float w2 = __shfl_sync(0xFFFFFFFFu, w, j + 2);
            float w3 = __shfl_sync(0xFFFFFFFFu, w, j + 3);
            float w4 = __shfl_sync(0xFFFFFFFFu, w, j + 4);
            float w5 = __shfl_sync(0xFFFFFFFFu, w, j + 5);
            float w6 = __shfl_sync(0xFFFFFFFFu, w, j + 6);
            float w7 = __shfl_sync(0xFFFFFFFFu, w, j + 7);
            float4 v0 = __ldg((const float4*)(col + (size_t)s0 * 128));
            float4 v1 = __ldg((const float4*)(col + (size_t)s1 * 128));
            float4 v2 = __ldg((const float4*)(col + (size_t)s2 * 128));
            float4 v3 = __ldg((const float4*)(col + (size_t)s3 * 128));
            float4 v4 = __ldg((const float4*)(col + (size_t)s4 * 128));
            float4 v5 = __ldg((const float4*)(col + (size_t)s5 * 128));
            float4 v6 = __ldg((const float4*)(col + (size_t)s6 * 128));
            float4 v7 = __ldg((const float4*)(col + (size_t)s7 * 128));
            acc.x = fmaf(w0, v0.x, acc.x); acc.y = fmaf(w0, v0.y, acc.y);
            acc.z = fmaf(w0, v0.z, acc.z); acc.w = fmaf(w0, v0.w, acc.w);
            acc.x = fmaf(w1, v1.x, acc.x); acc.y = fmaf(w1, v1.y, acc.y);
            acc.z = fmaf(w1, v1.z, acc.z); acc.w = fmaf(w1, v1.w, acc.w);
            acc.x = fmaf(w2, v2.x, acc.x); acc.y = fmaf(w2, v2.y, acc.y);
            acc.z = fmaf(w2, v2.z, acc.z); acc.w = fmaf(w2, v2.w, acc.w);
            acc.x = fmaf(w3, v3.x, acc.x); acc.y = fmaf(w3, v3.y, acc.y);
            acc.z = fmaf(w3, v3.z, acc.z); acc.w = fmaf(w3, v3.w, acc.w);
            acc.x = fmaf(w4, v4.x, acc.x); acc.y = fmaf(w4, v4.y, acc.y);
            acc.z = fmaf(w4, v4.z, acc.z); acc.w = fmaf(w4, v4.w, acc.w);
            acc.x = fmaf(w5, v5.x, acc.x); acc.y = fmaf(w5, v5.y, acc.y);
            acc.z = fmaf(w5, v5.z, acc.z); acc.w = fmaf(w5, v5.w, acc.w);
            acc.x = fmaf(w6, v6.x, acc.x); acc.y = fmaf(w6, v6.y, acc.y);
            acc.z = fmaf(w6, v6.z, acc.z); acc.w = fmaf(w6, v6.w, acc.w);
            acc.x = fmaf(w7, v7.x, acc.x); acc.y = fmaf(w7, v7.y, acc.y);
            acc.z = fmaf(w7, v7.z, acc.z); acc.w = fmaf(w7, v7.w, acc.w);
        }
        for (; j < c; j++) {
            int   sj = __shfl_sync(0xFFFFFFFFu, s, j);
            float wj = __shfl_sync(0xFFFFFFFFu, w, j);
            float4 v = __ldg((const float4*)(col + (size_t)sj * 128));
            acc.x = fmaf(wj, v.x, acc.x); acc.y = fmaf(wj, v.y, acc.y);
            acc.z = fmaf(wj, v.z, acc.z); acc.w = fmaf(wj, v.w, acc.w);
        }
        s = sn; w = wn;
    }
    *(float4*)(outp + (size_t)n * 128 + lane * 4) = acc;
}

// ---------------- SpMM d=16: 4 threads/node, float4 lanes; 32 nodes per 128-thread block ----------------
__global__ void k_spmm16(const float* __restrict__ inp, float* __restrict__ outp) {
    int node = blockIdx.x * 32 + (threadIdx.x >> 2);
    int c4   = threadIdx.x & 3;
    if (node >= NN) return;
    int start = __ldg(&g_rowoff[node]), end = __ldg(&g_rowoff[node + 1]);
    const float* col = inp + c4 * 4;
    float4 acc = make_float4(0.f, 0.f, 0.f, 0.f);
    int i = start;
    for (; i + 4 <= end; i += 4) {
        int2 e0 = __ldg(&g_csr[i + 0]);
        int2 e1 = __ldg(&g_csr[i + 1]);
        int2 e2 = __ldg(&g_csr[i + 2]);
        int2 e3 = __ldg(&g_csr[i + 3]);
        float4 v0 = __ldg((const float4*)(col + (size_t)e0.x * 16));
        float4 v1 = __ldg((const float4*)(col + (size_t)e1.x * 16));
        float4 v2 = __ldg((const float4*)(col + (size_t)e2.x * 16));
        float4 v3 = __ldg((const float4*)(col + (size_t)e3.x * 16));
        float w0 = __int_as_float(e0.y), w1 = __int_as_float(e1.y);
        float w2 = __int_as_float(e2.y), w3 = __int_as_float(e3.y);
        acc.x = fmaf(w0, v0.x, acc.x); acc.y = fmaf(w0, v0.y, acc.y);
        acc.z = fmaf(w0, v0.z, acc.z); acc.w = fmaf(w0, v0.w, acc.w);
        acc.x = fmaf(w1, v1.x, acc.x); acc.y = fmaf(w1, v1.y, acc.y);
        acc.z = fmaf(w1, v1.z, acc.z); acc.w = fmaf(w1, v1.w, acc.w);
        acc.x = fmaf(w2, v2.x, acc.x); acc.y = fmaf(w2, v2.y, acc.y);
        acc.z = fmaf(w2, v2.z, acc.z); acc.w = fmaf(w2, v2.w, acc.w);
        acc.x = fmaf(w3, v3.x, acc.x); acc.y = fmaf(w3, v3.y, acc.y);
        acc.z = fmaf(w3, v3.z, acc.z); acc.w = fmaf(w3, v3.w, acc.w);
    }
    for (; i < end; i++) {
        int2 e = __ldg(&g_csr[i]);
        float w = __int_as_float(e.y);
        float4 v = __ldg((const float4*)(col + (size_t)e.x * 16));
        acc.x = fmaf(w, v.x, acc.x); acc.y = fmaf(w, v.y, acc.y);
        acc.z = fmaf(w, v.z, acc.z); acc.w = fmaf(w, v.w, acc.w);
    }
    *(float4*)(outp + (size_t)node * 16 + c4 * 4) = acc;
}

// ---------------- SpMM d=4 with addend: out[n] = add[n] + sum_e w*in[src] ----------------
__global__ void __launch_bounds__(256)
k_spmm4(const float* __restrict__ in, int in_stride,
        const float* __restrict__ add, int add_stride,
        float* __restrict__ outp, int out_stride) {
    int lane = threadIdx.x & 31;
    int n = blockIdx.x * 8 + (threadIdx.x >> 5);     // NN % 8 == 0
    int start = __ldg(&g_rowoff[n]), end = __ldg(&g_rowoff[n + 1]);
    float4 acc = make_float4(0.f, 0.f, 0.f, 0.f);
    for (int i = start + lane; i < end; i += 32) {
        int2 e = __ldg(&g_csr[i]);
        float w = __int_as_float(e.y);
        float4 v = __ldg((const float4*)(in + (size_t)e.x * in_stride));
        acc.x = fmaf(w, v.x, acc.x); acc.y = fmaf(w, v.y, acc.y);
        acc.z = fmaf(w, v.z, acc.z); acc.w = fmaf(w, v.w, acc.w);
    }
    #pragma unroll
    for (int off = 16; off; off >>= 1) {
        acc.x += __shfl_xor_sync(0xFFFFFFFFu, acc.x, off);
        acc.y += __shfl_xor_sync(0xFFFFFFFFu, acc.y, off);
        acc.z += __shfl_xor_sync(0xFFFFFFFFu, acc.z, off);
        acc.w += __shfl_xor_sync(0xFFFFFFFFu, acc.w, off);
    }
    if (lane == 0) {
        float4 a = *(const float4*)(add + (size_t)n * add_stride);
        acc.x += a.x; acc.y += a.y; acc.z += a.z; acc.w += a.w;
        *(float4*)(outp + (size_t)n * out_stride) = acc;
    }
}

// ---------------- layer-3 projection: P[n, k*4+j] = h[n,:] @ W3[k,:,j]  (+ b3 folded into k=0) ----------------
__global__ void __launch_bounds__(256)
k_proj16(const float* __restrict__ h, const float* __restrict__ W3,
         const float* __restrict__ b3, float* __restrict__ P) {
    int lane = threadIdx.x & 31;
    int n = blockIdx.x * 8 + (threadIdx.x >> 5);     // NN % 8 == 0
    float acc[16];
    #pragma unroll
    for (int q = 0; q < 16; q++) acc[q] = 0.f;
    if (lane == 0) {  // bias folded into k=0; reduction sums lanes
        acc[0] = b3[0]; acc[1] = b3[1]; acc[2] = b3[2]; acc[3] = b3[3];
    }
    #pragma unroll
    for (int i = 0; i < 4; i++) {
        int c = lane + 32 * i;
        float hv = __ldg(h + (size_t)n * 128 + c);
        #pragma unroll
        for (int k = 0; k < 4; k++) {
            float4 wv = __ldg((const float4*)(W3 + (size_t)k * 512 + c * 4));
            acc[k * 4 + 0] = fmaf(hv, wv.x, acc[k * 4 + 0]);
            acc[k * 4 + 1] = fmaf(hv, wv.y, acc[k * 4 + 1]);
            acc[k * 4 + 2] = fmaf(hv, wv.z, acc[k * 4 + 2]);
            acc[k * 4 + 3] = fmaf(hv, wv.w, acc[k * 4 + 3]);
        }
    }
    #pragma unroll
    for (int q = 0; q < 16; q++) {
        #pragma unroll
        for (int off = 16; off; off >>= 1)
            acc[q] += __shfl_xor_sync(0xFFFFFFFFu, acc[q], off);
    }
    if (lane == 0) {
        #pragma unroll
        for (int q = 0; q < 16; q += 4) {
            float4 v = make_float4(acc[q], acc[q + 1], acc[q + 2], acc[q + 3]);
            *(float4*)(P + (size_t)n * 16 + q) = v;
        }
    }
}

// ---------------- fused concat-K GEMM (double-buffered): out = [A0|A1|A2|A3] @ W + b ----------------
// W is (4*DIN, 128) row-major
template <int DIN, bool RELU>
__global__ void __launch_bounds__(256)
k_gemm(const float* __restrict__ A0, const float* __restrict__ A1,
       const float* __restrict__ A2, const float* __restrict__ A3,
       const float* __restrict__ W, const float* __restrict__ bias,
       float* __restrict__ outp) {
    constexpr int BM = 128, BN = 128, BK = 16, KTOT = 4 * DIN;
    constexpr int NT = KTOT / BK;
    __shared__ float As[2][BK][BM];
    __shared__ float Bs[2][BK][BN];
    int tid = threadIdx.x;
    int ty = tid >> 4, tx = tid & 15;
    int rowBase = blockIdx.x * BM;

    // per-thread load coordinates (2 float4 each for A and B)
    int arow0 = (tid + 0)   >> 2, ac4_0 = (tid + 0)   & 3;
    int arow1 = (tid + 256) >> 2, ac4_1 = (tid + 256) & 3;
    int brow0 = (tid + 0)   >> 5, bc4_0 = (tid + 0)   & 31;
    int brow1 = (tid + 256) >> 5, bc4_1 = (tid + 256) & 31;

    auto ldA = [&](int kk0, float4& va0, float4& va1) {
        const float* Ak = (kk0 < DIN) ? A0 : (kk0 < 2 * DIN) ? A1 : (kk0 < 3 * DIN) ? A2 : A3;
        int off = kk0 & (DIN - 1);
        int gr0 = rowBase + arow0;
        int gr1 = rowBase + arow1;
        va0 = make_float4(0.f, 0.f, 0.f, 0.f);
        va1 = make_float4(0.f, 0.f, 0.f, 0.f);
        if (gr0 < NN) va0 = *(const float4*)(Ak + (size_t)gr0 * DIN + off + ac4_0 * 4);
        if (gr1 < NN) va1 = *(const float4*)(Ak + (size_t)gr1 * DIN + off + ac4_1 * 4);
    };
    auto ldB = [&](int kk0, float4& vb0, float4& vb1) {
        vb0 = *(const float4*)(W + (size_t)(kk0 + brow0) * BN + bc4_0 * 4);
        vb1 = *(const float4*)(W + (size_t)(kk0 + brow1) * BN + bc4_1 * 4);
    };
    auto stTile = [&](int buf, float4 va0, float4 va1, float4 vb0, float4 vb1) {
        As[buf][ac4_0 * 4 + 0][arow0] = va0.x;
        As[buf][ac4_0 * 4 + 1][arow0] = va0.y;
        As[buf][ac4_0 * 4 + 2][arow0] = va0.z;
        As[buf][ac4_0 * 4 + 3][arow0] = va0.w;
        As[buf][ac4_1 * 4 + 0][arow1] = va1.x;
        As[buf][ac4_1 * 4 + 1][arow1] = va1.y;
        As[buf][ac4_1 * 4 + 2][arow1] = va1.z;
        As[buf][ac4_1 * 4 + 3][arow1] = va1.w;
        *(float4*)(&Bs[buf][brow0][bc4_0 * 4]) = vb0;
        *(float4*)(&Bs[buf][brow1][bc4_1 * 4]) = vb1;
    };

    float acc[8][8];
    #pragma unroll
    for (int i = 0; i < 8; i++)
        #pragma unroll
        for (int j = 0; j < 8; j++) acc[i][j] = 0.f;

    {   // prologue: tile 0 -> buf 0
        float4 va0, va1, vb0, vb1;
        ldA(0, va0, va1);
        ldB(0, vb0, vb1);
        stTile(0, va0, va1, vb0, vb1);
    }
    __syncthreads();

    for (int t = 0; t < NT; t++) {
        int cur = t & 1;
        float4 va0, va1, vb0, vb1;
        bool more = (t + 1 < NT);
        if (more) {
            ldA((t + 1) * BK, va0, va1);
            ldB((t + 1) * BK, vb0, vb1);
        }
        #pragma unroll
        for (int k = 0; k < BK; k++) {
            float4 ra0 = *(const float4*)(&As[cur][k][ty * 8 + 0]);
            float4 ra1 = *(const float4*)(&As[cur][k][ty * 8 + 4]);
            float4 rb0 = *(const float4*)(&Bs[cur][k][tx * 8 + 0]);
            float4 rb1 = *(const float4*)(&Bs[cur][k][tx * 8 + 4]);
            float ra[8] = {ra0.x, ra0.y, ra0.z, ra0.w, ra1.x, ra1.y, ra1.z, ra1.w};
            float rb[8] = {rb0.x, rb0.y, rb0.z, rb0.w, rb1.x, rb1.y, rb1.z, rb1.w};
            #pragma unroll
            for (int i = 0; i < 8; i++)
                #pragma unroll
                for (int j = 0; j < 8; j++)
                    acc[i][j] = fmaf(ra[i], rb[j], acc[i][j]);
        }
        if (more) {
            stTile(cur ^ 1, va0, va1, vb0, vb1);
            __syncthreads();
        }
    }

    #pragma unroll
    for (int i = 0; i < 8; i++) {
        int gr = rowBase + ty * 8 + i;
        if (gr < NN) {
            #pragma unroll
            for (int j = 0; j < 8; j += 4) {
                int gc = tx * 8 + j;
                float4 v;
                v.x = acc[i][j + 0] + bias[gc + 0];
                v.y = acc[i][j + 1] + bias[gc + 1];
                v.z = acc[i][j + 2] + bias[gc + 2];
                v.w = acc[i][j + 3] + bias[gc + 3];
                if (RELU) {
                    v.x = fmaxf(v.x, 0.f); v.y = fmaxf(v.y, 0.f);
                    v.z = fmaxf(v.z, 0.f); v.w = fmaxf(v.w, 0.f);
                }
                *(float4*)(outp + (size_t)gr * 128 + gc) = v;
            }
        }
    }
}

// ---------------- launch ----------------
extern "C" void kernel_launch(void* const* d_in, const int* in_sizes, int n_in,
                              void* d_out, int out_size) {
    const float* x  = (const float*)d_in[0];
    const void*  ei = d_in[1];               // int32 or int64, probed on device
    const float* ew = (const float*)d_in[2];
    const float* W0 = (const float*)d_in[3];
    const float* b0 = (const float*)d_in[4];
    const float* W1 = (const float*)d_in[5];
    const float* b1 = (const float*)d_in[6];
    const float* W2 = (const float*)d_in[7];
    const float* b2 = (const float*)d_in[8];
    const float* W3 = (const float*)d_in[9];
    const float* b3 = (const float*)d_in[10];
    float* out = (float*)d_out;

    float *Hp, *OA, *OB;
    cudaGetSymbolAddress((void**)&Hp, g_H);
    cudaGetSymbolAddress((void**)&OA, g_OutA);
    cudaGetSymbolAddress((void**)&OB, g_OutB);
    float* H1 = Hp;
    float* H2 = Hp + (size_t)NN * 128;
    float* H3 = Hp + (size_t)2 * NN * 128;

    const int NB256 = (NN + 255) / 256;      // 391
    const int EB256 = (EE + 255) / 256;      // 12500
    const int NSCAN = (NN + 1023) / 1024;    // 98
    const int GEMMB = (NN + 127) / 128;      // 782
    const int WPB8  = NN / 8;                // 12500 (warp-per-node kernels)

    // preprocessing: dtype probe -> degree -> CSR (counting sort by dst)
    k_detect<<<1, 256>>>(ei);
    k_zero<<<NB256, 256>>>();
    k_deg<<<EB256, 256>>>(ei, ew);
    k_scan1<<<NSCAN, 1024>>>();
    k_scan2<<<1, 128>>>(NSCAN);
    k_scan3<<<NB256, 256>>>();
    k_fill<<<EB256, 256>>>(ei, ew);

    // layer 0: din=16 -> 128, relu (propagate at d=16, then concat-GEMM)
    float* h1_16 = H1;
    float* h2_16 = H1 + (size_t)NN * 16;
    float* h3_16 = H1 + (size_t)NN * 32;
    k_spmm16<<<(NN + 31) / 32, 128>>>(x, h1_16);
    k_spmm16<<<(NN + 31) / 32, 128>>>(h1_16, h2_16);
    k_spmm16<<<(NN + 31) / 32, 128>>>(h2_16, h3_16);
    k_gemm<16, true><<<GEMMB, 256>>>(x, h1_16, h2_16, h3_16, W0, b0, OA);

    // layer 1: 128 -> 128, relu
    k_spmm128<<<WPB8, 256>>>(OA, H1);
    k_spmm128<<<WPB8, 256>>>(H1, H2);
    k_spmm128<<<WPB8, 256>>>(H2, H3);
    k_gemm<128, true><<<GEMMB, 256>>>(OA, H1, H2, H3, W1, b1, OB);

    // layer 2: 128 -> 128, relu
    k_spmm128<<<WPB8, 256>>>(OB, H1);
    k_spmm128<<<WPB8, 256>>>(H1, H2);
    k_spmm128<<<WPB8, 256>>>(H2, H3);
    k_gemm<128, true><<<GEMMB, 256>>>(OB, H1, H2, H3, W2, b2, OA);

    // layer 3 (dout=4): project FIRST, then propagate at d=4.
    // out = P0 + A(P1 + A(P2 + A(P3))),  P = OA @ W3 (N x 16), b3 folded into P0.
    float* P  = H1;                          // N*16
    float* T3 = H1 + (size_t)NN * 16;        // N*4
    float* T2 = H1 + (size_t)NN * 20;        // N*4
    k_proj16<<<WPB8, 256>>>(OA, W3, b3, P);
    k_spmm4<<<WPB8, 256>>>(P + 12, 16, P + 8, 16, T3, 4);   // T3 = A*P3 + P2
    k_spmm4<<<WPB8, 256>>>(T3, 4, P + 4, 16, T2, 4);        // T2 = A*T3 + P1
    k_spmm4<<<WPB8, 256>>>(T2, 4, P + 0, 16, out, 4);       // out = A*T2 + P0(+b3)
}

// round 12
// speedup vs baseline: 1.1321x; 1.1321x over previous
#include <cuda_runtime.h>
#include <cuda_bf16.h>

#define NN 100000
#define EE 3200000

// ---------------- static device scratch (no cudaMalloc allowed) ----------------
__device__ float g_deg[NN];
__device__ float g_dis[NN];
__device__ int   g_cnt[NN];
__device__ int   g_rowoff[NN + 1];
__device__ int   g_cursor[NN];
__device__ int   g_bsum[128];
__device__ int   g_is32;                 // 1 if edge_index is int32, 0 if int64
__device__ int2  g_csr[EE];              // packed {src, float_bits(norm_w)}
__device__ float g_H[3 * NN * 128];      // hop buffers h1..h3 (max d=128); also P/T for layer 3
__device__ float g_OutA[NN * 128];
__device__ float g_OutB[NN * 128];

// ---------------- dtype probe: is edge_index int32 or int64? ----------------
__global__ void k_detect(const void* ei) {
    const long long* p = (const long long*)ei;
    long long v = p[threadIdx.x];
    int bad = (v < 0 || v >= NN) ? 1 : 0;
    int any = __syncthreads_or(bad);
    if (threadIdx.x == 0) g_is32 = any;
}

__device__ __forceinline__ void load_edge(const void* ei, int e, int& s, int& d) {
    if (g_is32) {
        const int* p = (const int*)ei;
        s = p[e];
        d = p[EE + e];
    } else {
        const long long* p = (const long long*)ei;
        s = (int)p[e];
        d = (int)p[(size_t)EE + e];
    }
}

// ---------------- preprocessing ----------------
__global__ void k_zero() {
    int i = blockIdx.x * blockDim.x + threadIdx.x;
    if (i < NN) { g_deg[i] = 0.f; g_cnt[i] = 0; }
}

__global__ void k_deg(const void* ei, const float* __restrict__ w) {
    int e = blockIdx.x * blockDim.x + threadIdx.x;
    if (e < EE) {
        int s, d;
        load_edge(ei, e, s, d);
        atomicAdd(&g_deg[d], w[e]);
        atomicAdd(&g_cnt[d], 1);
    }
}

// 3-kernel exclusive scan of g_cnt -> g_rowoff (dis folded into scan3)
__global__ void k_scan1() {
    __shared__ int s[1024];
    int t = threadIdx.x, b = blockIdx.x;
    int i = b * 1024 + t;
    int v = (i < NN) ? g_cnt[i] : 0;
    s[t] = v; __syncthreads();
    #pragma unroll
    for (int off = 1; off < 1024; off <<= 1) {
        int add = (t >= off) ? s[t - off] : 0;
        __syncthreads();
        s[t] += add;
        __syncthreads();
    }
    if (i < NN) g_rowoff[i] = s[t] - v;   // exclusive within block
    if (t == 1023) g_bsum[b] = s[1023];
}

__global__ void k_scan2(int nblk) {
    __shared__ int s[128];
    int t = threadIdx.x;
    int v = (t < nblk) ? g_bsum[t] : 0;
    s[t] = v; __syncthreads();
    #pragma unroll
    for (int off = 1; off < 128; off <<= 1) {
        int add = (t >= off) ? s[t - off] : 0;
        __syncthreads();
        s[t] += add;
        __syncthreads();
    }
    g_bsum[t] = s[t] - v;                  // exclusive
}

__global__ void k_scan3() {
    int i = blockIdx.x * blockDim.x + threadIdx.x;
    if (i < NN) {
        int v = g_rowoff[i] + g_bsum[i >> 10];
        g_rowoff[i] = v;
        g_cursor[i] = v;
        float dg = g_deg[i];
        g_dis[i] = (dg > 0.f) ? rsqrtf(dg) : 0.f;
    }
    if (i == 0) g_rowoff[NN] = EE;
}

__global__ void k_fill(const void* ei, const float* __restrict__ w) {
    int e = blockIdx.x * blockDim.x + threadIdx.x;
    if (e < EE) {
        int s, d;
        load_edge(ei, e, s, d);
        float nr = g_dis[s] * w[e] * g_dis[d];
        int pos = atomicAdd(&g_cursor[d], 1);
        g_csr[pos] = make_int2(s, __float_as_int(nr));
    }
}

// ---------------- SpMM d=128: warp per node, float4 gathers, 8-edge shfl broadcast,
//                  edge-tile prefetch pipeline ----------------
__global__ void __launch_bounds__(256)
k_spmm128(const float* __restrict__ inp, float* __restrict__ outp) {
    int lane = threadIdx.x & 31;
    int n = blockIdx.x * 8 + (threadIdx.x >> 5);     // NN % 8 == 0
    int start = __ldg(&g_rowoff[n]), end = __ldg(&g_rowoff[n + 1]);
    float4 acc = make_float4(0.f, 0.f, 0.f, 0.f);
    const float* col = inp + lane * 4;

    int s = 0; float w = 0.f;
    {
        int i = start + lane;
        if (i < end) {
            int2 e = __ldg(&g_csr[i]);
            s = e.x; w = __int_as_float(e.y);
        }
    }
    for (int base = start; base < end; base += 32) {
        int sn = 0; float wn = 0.f;
        int inext = base + 32 + lane;
        if (inext < end) {
            int2 e = __ldg(&g_csr[inext]);
            sn = e.x; wn = __int_as_float(e.y);
        }
        int c = min(32, end - base);
        int j = 0;
        for (; j + 8 <= c; j += 8) {
            int   s0 = __shfl_sync(0xFFFFFFFFu, s, j + 0);
            int   s1 = __shfl_sync(0xFFFFFFFFu, s, j + 1);
            int   s2 = __shfl_sync(0xFFFFFFFFu, s, j + 2);
            int   s3 = __shfl_sync(0xFFFFFFFFu, s, j + 3);
            int   s4 = __shfl_sync(0xFFFFFFFFu, s, j + 4);
            int   s5 = __shfl_sync(0xFFFFFFFFu, s, j + 5);
            int   s6 = __shfl_sync(0xFFFFFFFFu, s, j + 6);
            int   s7 = __shfl_sync(0xFFFFFFFFu, s, j + 7);
            float w0 = __shfl_sync(0xFFFFFFFFu, w, j + 0);
            float w1 = __shfl_sync(0xFFFFFFFFu, w, j + 1);
            float w2 = __shfl_sync(0xFFFFFFFFu, w, j + 2);
            float w3 = __shfl_sync(0xFFFFFFFFu, w, j + 3);
            float w4 = __shfl_sync(0xFFFFFFFFu, w, j + 4);
            float w5 = __shfl_sync(0xFFFFFFFFu, w, j + 5);
            float w6 = __shfl_sync(0xFFFFFFFFu, w, j + 6);
            float w7 = __shfl_sync(0xFFFFFFFFu, w, j + 7);
            float4 v0 = __ldg((const float4*)(col + (size_t)s0 * 128));
            float4 v1 = __ldg((const float4*)(col + (size_t)s1 * 128));
            float4 v2 = __ldg((const float4*)(col + (size_t)s2 * 128));
            float4 v3 = __ldg((const float4*)(col + (size_t)s3 * 128));
            float4 v4 = __ldg((const float4*)(col + (size_t)s4 * 128));
            float4 v5 = __ldg((const float4*)(col + (size_t)s5 * 128));
            float4 v6 = __ldg((const float4*)(col + (size_t)s6 * 128));
            float4 v7 = __ldg((const float4*)(col + (size_t)s7 * 128));
            acc.x = fmaf(w0, v0.x, acc.x); acc.y = fmaf(w0, v0.y, acc.y);
            acc.z = fmaf(w0, v0.z, acc.z); acc.w = fmaf(w0, v0.w, acc.w);
            acc.x = fmaf(w1, v1.x, acc.x); acc.y = fmaf(w1, v1.y, acc.y);
            acc.z = fmaf(w1, v1.z, acc.z); acc.w = fmaf(w1, v1.w, acc.w);
            acc.x = fmaf(w2, v2.x, acc.x); acc.y = fmaf(w2, v2.y, acc.y);
            acc.z = fmaf(w2, v2.z, acc.z); acc.w = fmaf(w2, v2.w, acc.w);
            acc.x = fmaf(w3, v3.x, acc.x); acc.y = fmaf(w3, v3.y, acc.y);
            acc.z = fmaf(w3, v3.z, acc.z); acc.w = fmaf(w3, v3.w, acc.w);
            acc.x = fmaf(w4, v4.x, acc.x); acc.y = fmaf(w4, v4.y, acc.y);
            acc.z = fmaf(w4, v4.z, acc.z); acc.w = fmaf(w4, v4.w, acc.w);
            acc.x = fmaf(w5, v5.x, acc.x); acc.y = fmaf(w5, v5.y, acc.y);
            acc.z = fmaf(w5, v5.z, acc.z); acc.w = fmaf(w5, v5.w, acc.w);
            acc.x = fmaf(w6, v6.x, acc.x); acc.y = fmaf(w6, v6.y, acc.y);
            acc.z = fmaf(w6, v6.z, acc.z); acc.w = fmaf(w6, v6.w, acc.w);
            acc.x = fmaf(w7, v7.x, acc.x); acc.y = fmaf(w7, v7.y, acc.y);
            acc.z = fmaf(w7, v7.z, acc.z); acc.w = fmaf(w7, v7.w, acc.w);
        }
        for (; j < c; j++) {
            int   sj = __shfl_sync(0xFFFFFFFFu, s, j);
            float wj = __shfl_sync(0xFFFFFFFFu, w, j);
            float4 v = __ldg((const float4*)(col + (size_t)sj * 128));
            acc.x = fmaf(wj, v.x, acc.x); acc.y = fmaf(wj, v.y, acc.y);
            acc.z = fmaf(wj, v.z, acc.z); acc.w = fmaf(wj, v.w, acc.w);
        }
        s = sn; w = wn;
    }
    *(float4*)(outp + (size_t)n * 128 + lane * 4) = acc;
}

// ---------------- SpMM d=16: 4 threads/node, float4 lanes; 32 nodes per 128-thread block ----------------
__global__ void k_spmm16(const float* __restrict__ inp, float* __restrict__ outp) {
    int node = blockIdx.x * 32 + (threadIdx.x >> 2);
    int c4   = threadIdx.x & 3;
    if (node >= NN) return;
    int start = __ldg(&g_rowoff[node]), end = __ldg(&g_rowoff[node + 1]);
    const float* col = inp + c4 * 4;
    float4 acc = make_float4(0.f, 0.f, 0.f, 0.f);
    int i = start;
    for (; i + 4 <= end; i += 4) {
        int2 e0 = __ldg(&g_csr[i + 0]);
        int2 e1 = __ldg(&g_csr[i + 1]);
        int2 e2 = __ldg(&g_csr[i + 2]);
        int2 e3 = __ldg(&g_csr[i + 3]);
        float4 v0 = __ldg((const float4*)(col + (size_t)e0.x * 16));
        float4 v1 = __ldg((const float4*)(col + (size_t)e1.x * 16));
        float4 v2 = __ldg((const float4*)(col + (size_t)e2.x * 16));
        float4 v3 = __ldg((const float4*)(col + (size_t)e3.x * 16));
        float w0 = __int_as_float(e0.y), w1 = __int_as_float(e1.y);
        float w2 = __int_as_float(e2.y), w3 = __int_as_float(e3.y);
        acc.x = fmaf(w0, v0.x, acc.x); acc.y = fmaf(w0, v0.y, acc.y);
        acc.z = fmaf(w0, v0.z, acc.z); acc.w = fmaf(w0, v0.w, acc.w);
        acc.x = fmaf(w1, v1.x, acc.x); acc.y = fmaf(w1, v1.y, acc.y);
        acc.z = fmaf(w1, v1.z, acc.z); acc.w = fmaf(w1, v1.w, acc.w);
        acc.x = fmaf(w2, v2.x, acc.x); acc.y = fmaf(w2, v2.y, acc.y);
        acc.z = fmaf(w2, v2.z, acc.z); acc.w = fmaf(w2, v2.w, acc.w);
        acc.x = fmaf(w3, v3.x, acc.x); acc.y = fmaf(w3, v3.y, acc.y);
        acc.z = fmaf(w3, v3.z, acc.z); acc.w = fmaf(w3, v3.w, acc.w);
    }
    for (; i < end; i++) {
        int2 e = __ldg(&g_csr[i]);
        float w = __int_as_float(e.y);
        float4 v = __ldg((const float4*)(col + (size_t)e.x * 16));
        acc.x = fmaf(w, v.x, acc.x); acc.y = fmaf(w, v.y, acc.y);
        acc.z = fmaf(w, v.z, acc.z); acc.w = fmaf(w, v.w, acc.w);
    }
    *(float4*)(outp + (size_t)node * 16 + c4 * 4) = acc;
}

// ---------------- SpMM d=4 with addend: out[n] = add[n] + sum_e w*in[src] ----------------
__global__ void __launch_bounds__(256)
k_spmm4(const float* __restrict__ in, int in_stride,
        const float* __restrict__ add, int add_stride,
        float* __restrict__ outp, int out_stride) {
    int lane = threadIdx.x & 31;
    int n = blockIdx.x * 8 + (threadIdx.x >> 5);     // NN % 8 == 0
    int start = __ldg(&g_rowoff[n]), end = __ldg(&g_rowoff[n + 1]);
    float4 acc = make_float4(0.f, 0.f, 0.f, 0.f);
    for (int i = start + lane; i < end; i += 32) {
        int2 e = __ldg(&g_csr[i]);
        float w = __int_as_float(e.y);
        float4 v = __ldg((const float4*)(in + (size_t)e.x * in_stride));
        acc.x = fmaf(w, v.x, acc.x); acc.y = fmaf(w, v.y, acc.y);
        acc.z = fmaf(w, v.z, acc.z); acc.w = fmaf(w, v.w, acc.w);
    }
    #pragma unroll
    for (int off = 16; off; off >>= 1) {
        acc.x += __shfl_xor_sync(0xFFFFFFFFu, acc.x, off);
        acc.y += __shfl_xor_sync(0xFFFFFFFFu, acc.y, off);
        acc.z += __shfl_xor_sync(0xFFFFFFFFu, acc.z, off);
        acc.w += __shfl_xor_sync(0xFFFFFFFFu, acc.w, off);
    }
    if (lane == 0) {
        float4 a = *(const float4*)(add + (size_t)n * add_stride);
        acc.x += a.x; acc.y += a.y; acc.z += a.z; acc.w += a.w;
        *(float4*)(outp + (size_t)n * out_stride) = acc;
    }
}

// ---------------- layer-3 projection: P[n, k*4+j] = h[n,:] @ W3[k,:,j]  (+ b3 folded into k=0) ----------------
__global__ void __launch_bounds__(256)
k_proj16(const float* __restrict__ h, const float* __restrict__ W3,
         const float* __restrict__ b3, float* __restrict__ P) {
    int lane = threadIdx.x & 31;
    int n = blockIdx.x * 8 + (threadIdx.x >> 5);     // NN % 8 == 0
    float acc[16];
    #pragma unroll
    for (int q = 0; q < 16; q++) acc[q] = 0.f;
    if (lane == 0) {  // bias folded into k=0; reduction sums lanes
        acc[0] = b3[0]; acc[1] = b3[1]; acc[2] = b3[2]; acc[3] = b3[3];
    }
    #pragma unroll
    for (int i = 0; i < 4; i++) {
        int c = lane + 32 * i;
        float hv = __ldg(h + (size_t)n * 128 + c);
        #pragma unroll
        for (int k = 0; k < 4; k++) {
            float4 wv = __ldg((const float4*)(W3 + (size_t)k * 512 + c * 4));
            acc[k * 4 + 0] = fmaf(hv, wv.x, acc[k * 4 + 0]);
            acc[k * 4 + 1] = fmaf(hv, wv.y, acc[k * 4 + 1]);
            acc[k * 4 + 2] = fmaf(hv, wv.z, acc[k * 4 + 2]);
            acc[k * 4 + 3] = fmaf(hv, wv.w, acc[k * 4 + 3]);
        }
    }
    #pragma unroll
    for (int q = 0; q < 16; q++) {
        #pragma unroll
        for (int off = 16; off; off >>= 1)
            acc[q] += __shfl_xor_sync(0xFFFFFFFFu, acc[q], off);
    }
    if (lane == 0) {
        #pragma unroll
        for (int q = 0; q < 16; q += 4) {
            float4 v = make_float4(acc[q], acc[q + 1], acc[q + 2], acc[q + 3]);
            *(float4*)(P + (size_t)n * 16 + q) = v;
        }
    }
}

// ---------------- tf32 helpers ----------------
__device__ __forceinline__ float tf32f(float x) {
    unsigned r;
    asm("cvt.rna.tf32.f32 %0, %1;" : "=r"(r) : "f"(x));
    return __uint_as_float(r);
}

__device__ __forceinline__ void mma_tf32(float* d, const unsigned* a, const unsigned* b) {
    asm volatile(
        "mma.sync.aligned.m16n8k8.row.col.f32.tf32.tf32.f32 "
        "{%0,%1,%2,%3}, {%4,%5,%6,%7}, {%8,%9}, {%0,%1,%2,%3};\n"
        : "+f"(d[0]), "+f"(d[1]), "+f"(d[2]), "+f"(d[3])
        : "r"(a[0]), "r"(a[1]), "r"(a[2]), "r"(a[3]), "r"(b[0]), "r"(b[1]));
}

// ---------------- tensor-core concat-K GEMM (3xTF32): out = [A0|A1|A2|A3] @ W + b ----------------
// A operands fp32 split to tf32 hi/lo at the smem stage; W (4*DIN,128) row-major staged [n][k].
// Accuracy ~fp32 (hi*hi + hi*lo + lo*hi). All smem stores are float4 along k (conflict-free).
template <int DIN, bool RELU>
__global__ void __launch_bounds__(256)
k_gemm_tc(const float* __restrict__ A0, const float* __restrict__ A1,
          const float* __restrict__ A2, const float* __restrict__ A3,
          const float* __restrict__ W, const float* __restrict__ bias,
          float* __restrict__ outp) {
    constexpr int BM = 128, BN = 128, BK = 16, KTOT = 4 * DIN;
    constexpr int NT = KTOT / BK;
    constexpr int PAD = 20;                  // row stride (floats); frag loads conflict-free
    __shared__ float As_hi[BM][PAD], As_lo[BM][PAD];   // [m][k]
    __shared__ float Bs_hi[BN][PAD], Bs_lo[BN][PAD];   // [n][k]

    int tid = threadIdx.x;
    int lane = tid & 31;
    int gq = lane >> 2;          // 0..7
    int tg = lane & 3;           // 0..3
    int wid = tid >> 5;          // 0..7
    int mBase = (wid & 3) * 32;  // warp m-tile
    int nBase = (wid >> 2) * 64; // warp n-tile
    int rowBase = blockIdx.x * BM;

    // A global-load coordinates: 2 float4 per thread, [m][4k]
    int arow0 = (tid + 0)   >> 2, ac4_0 = (tid + 0)   & 3;
    int arow1 = (tid + 256) >> 2, ac4_1 = (tid + 256) & 3;
    // B: thread -> column n, 8 consecutive k
    int bn = tid & 127;
    int bkg = (tid >> 7) * 8;

    auto ldA = [&](int kk0, float4& va0, float4& va1) {
        const float* Ak = (kk0 < DIN) ? A0 : (kk0 < 2 * DIN) ? A1 : (kk0 < 3 * DIN) ? A2 : A3;
        int off = kk0 & (DIN - 1);
        int gr0 = rowBase + arow0;
        int gr1 = rowBase + arow1;
        va0 = make_float4(0.f, 0.f, 0.f, 0.f);
        va1 = make_float4(0.f, 0.f, 0.f, 0.f);
        if (gr0 < NN) va0 = *(const float4*)(Ak + (size_t)gr0 * DIN + off + ac4_0 * 4);
        if (gr1 < NN) va1 = *(const float4*)(Ak + (size_t)gr1 * DIN + off + ac4_1 * 4);
    };
    auto ldB = [&](int kk0, float* vb) {
        #pragma unroll
        for (int i = 0; i < 8; i++)
            vb[i] = __ldg(W + (size_t)(kk0 + bkg + i) * BN + bn);
    };
    auto stA4 = [&](int row, int kq, float4 v) {     // store 4 consecutive k, hi+lo
        float4 h, l;
        h.x = tf32f(v.x); l.x = tf32f(v.x - h.x);
        h.y = tf32f(v.y); l.y = tf32f(v.y - h.y);
        h.z = tf32f(v.z); l.z = tf32f(v.z - h.z);
        h.w = tf32f(v.w); l.w = tf32f(v.w - h.w);
        *(float4*)(&As_hi[row][kq * 4]) = h;
        *(float4*)(&As_lo[row][kq * 4]) = l;
    };
    auto stTile = [&](float4 va0, float4 va1, const float* vb) {
        stA4(arow0, ac4_0, va0);
        stA4(arow1, ac4_1, va1);
        float h[8], l[8];
        #pragma unroll
        for (int i = 0; i < 8; i++) { h[i] = tf32f(vb[i]); l[i] = tf32f(vb[i] - h[i]); }
        *(float4*)(&Bs_hi[bn][bkg + 0]) = make_float4(h[0], h[1], h[2], h[3]);
        *(float4*)(&Bs_hi[bn][bkg + 4]) = make_float4(h[4], h[5], h[6], h[7]);
        *(float4*)(&Bs_lo[bn][bkg + 0]) = make_float4(l[0], l[1], l[2], l[3]);
        *(float4*)(&Bs_lo[bn][bkg + 4]) = make_float4(l[4], l[5], l[6], l[7]);
    };

    float acc[2][8][4];
    #pragma unroll
    for (int mt = 0; mt < 2; mt++)
        #pragma unroll
        for (int nt = 0; nt < 8; nt++)
            #pragma unroll
            for (int q = 0; q < 4; q++) acc[mt][nt][q] = 0.f;

    float4 va0, va1;
    float vb[8];
    ldA(0, va0, va1);
    ldB(0, vb);

    for (int t = 0; t < NT; t++) {
        stTile(va0, va1, vb);
        __syncthreads();
        if (t + 1 < NT) {
            ldA((t + 1) * BK, va0, va1);
            ldB((t + 1) * BK, vb);
        }
        #pragma unroll
        for (int k8 = 0; k8 < 2; k8++) {
            int kb = k8 * 8;
            unsigned ahi[2][4], alo[2][4];
            #pragma unroll
            for (int mt = 0; mt < 2; mt++) {
                int m0 = mBase + mt * 16;
                ahi[mt][0] = __float_as_uint(As_hi[m0 + gq][kb + tg]);
                ahi[mt][1] = __float_as_uint(As_hi[m0 + gq + 8][kb + tg]);
                ahi[mt][2] = __float_as_uint(As_hi[m0 + gq][kb + tg + 4]);
                ahi[mt][3] = __float_as_uint(As_hi[m0 + gq + 8][kb + tg + 4]);
                alo[mt][0] = __float_as_uint(As_lo[m0 + gq][kb + tg]);
                alo[mt][1] = __float_as_uint(As_lo[m0 + gq + 8][kb + tg]);
                alo[mt][2] = __float_as_uint(As_lo[m0 + gq][kb + tg + 4]);
                alo[mt][3] = __float_as_uint(As_lo[m0 + gq + 8][kb + tg + 4]);
            }
            #pragma unroll
            for (int nt = 0; nt < 8; nt++) {
                int n0 = nBase + nt * 8;
                unsigned bhi[2], blo[2];
                bhi[0] = __float_as_uint(Bs_hi[n0 + gq][kb + tg]);
                bhi[1] = __float_as_uint(Bs_hi[n0 + gq][kb + tg + 4]);
                blo[0] = __float_as_uint(Bs_lo[n0 + gq][kb + tg]);
                blo[1] = __float_as_uint(Bs_lo[n0 + gq][kb + tg + 4]);
                #pragma unroll
                for (int mt = 0; mt < 2; mt++) {
                    mma_tf32(acc[mt][nt], ahi[mt], bhi);
                    mma_tf32(acc[mt][nt], ahi[mt], blo);
                    mma_tf32(acc[mt][nt], alo[mt], bhi);
                }
            }
        }
        __syncthreads();
    }

    // epilogue: D layout c0:(gq,2tg) c1:(gq,2tg+1) c2:(gq+8,2tg) c3:(gq+8,2tg+1)
    #pragma unroll
    for (int mt = 0; mt < 2; mt++) {
        #pragma unroll
        for (int r2 = 0; r2 < 2; r2++) {
            int gr = rowBase + mBase + mt * 16 + gq + r2 * 8;
            if (gr < NN) {
                #pragma unroll
                for (int nt = 0; nt < 8; nt++) {
                    int gc = nBase + nt * 8 + 2 * tg;
                    float2 v;
                    v.x = acc[mt][nt][r2 * 2 + 0] + bias[gc + 0];
                    v.y = acc[mt][nt][r2 * 2 + 1] + bias[gc + 1];
                    if (RELU) { v.x = fmaxf(v.x, 0.f); v.y = fmaxf(v.y, 0.f); }
                    *(float2*)(outp + (size_t)gr * 128 + gc) = v;
                }
            }
        }
    }
}

// ---------------- launch ----------------
extern "C" void kernel_launch(void* const* d_in, const int* in_sizes, int n_in,
                              void* d_out, int out_size) {
    const float* x  = (const float*)d_in[0];
    const void*  ei = d_in[1];               // int32 or int64, probed on device
    const float* ew = (const float*)d_in[2];
    const float* W0 = (const float*)d_in[3];
    const float* b0 = (const float*)d_in[4];
    const float* W1 = (const float*)d_in[5];
    const float* b1 = (const float*)d_in[6];
    const float* W2 = (const float*)d_in[7];
    const float* b2 = (const float*)d_in[8];
    const float* W3 = (const float*)d_in[9];
    const float* b3 = (const float*)d_in[10];
    float* out = (float*)d_out;

    float *Hp, *OA, *OB;
    cudaGetSymbolAddress((void**)&Hp, g_H);
    cudaGetSymbolAddress((void**)&OA, g_OutA);
    cudaGetSymbolAddress((void**)&OB, g_OutB);
    float* H1 = Hp;
    float* H2 = Hp + (size_t)NN * 128;
    float* H3 = Hp + (size_t)2 * NN * 128;

    const int NB256 = (NN + 255) / 256;      // 391
    const int EB256 = (EE + 255) / 256;      // 12500
    const int NSCAN = (NN + 1023) / 1024;    // 98
    const int GEMMB = (NN + 127) / 128;      // 782
    const int WPB8  = NN / 8;                // 12500 (warp-per-node kernels)

    // preprocessing: dtype probe -> degree -> CSR (counting sort by dst)
    k_detect<<<1, 256>>>(ei);
    k_zero<<<NB256, 256>>>();
    k_deg<<<EB256, 256>>>(ei, ew);
    k_scan1<<<NSCAN, 1024>>>();
    k_scan2<<<1, 128>>>(NSCAN);
    k_scan3<<<NB256, 256>>>();
    k_fill<<<EB256, 256>>>(ei, ew);

    // layer 0: din=16 -> 128, relu (propagate at d=16, then concat-GEMM)
    float* h1_16 = H1;
    float* h2_16 = H1 + (size_t)NN * 16;
    float* h3_16 = H1 + (size_t)NN * 32;
    k_spmm16<<<(NN + 31) / 32, 128>>>(x, h1_16);
    k_spmm16<<<(NN + 31) / 32, 128>>>(h1_16, h2_16);
    k_spmm16<<<(NN + 31) / 32, 128>>>(h2_16, h3_16);
    k_gemm_tc<16, true><<<GEMMB, 256>>>(x, h1_16, h2_16, h3_16, W0, b0, OA);

    // layer 1: 128 -> 128, relu
    k_spmm128<<<WPB8, 256>>>(OA, H1);
    k_spmm128<<<WPB8, 256>>>(H1, H2);
    k_spmm128<<<WPB8, 256>>>(H2, H3);
    k_gemm_tc<128, true><<<GEMMB, 256>>>(OA, H1, H2, H3, W1, b1, OB);

    // layer 2: 128 -> 128, relu
    k_spmm128<<<WPB8, 256>>>(OB, H1);
    k_spmm128<<<WPB8, 256>>>(H1, H2);
    k_spmm128<<<WPB8, 256>>>(H2, H3);
    k_gemm_tc<128, true><<<GEMMB, 256>>>(OB, H1, H2, H3, W2, b2, OA);

    // layer 3 (dout=4): project FIRST, then propagate at d=4.
    // out = P0 + A(P1 + A(P2 + A(P3))),  P = OA @ W3 (N x 16), b3 folded into P0.
    float* P  = H1;                          // N*16
    float* T3 = H1 + (size_t)NN * 16;        // N*4
    float* T2 = H1 + (size_t)NN * 20;        // N*4
    k_proj16<<<WPB8, 256>>>(OA, W3, b3, P);
    k_spmm4<<<WPB8, 256>>>(P + 12, 16, P + 8, 16, T3, 4);   // T3 = A*P3 + P2
    k_spmm4<<<WPB8, 256>>>(T3, 4, P + 4, 16, T2, 4);        // T2 = A*T3 + P1
    k_spmm4<<<WPB8, 256>>>(T2, 4, P + 0, 16, out, 4);       // out = A*T2 + P0(+b3)
}